// round 3
// baseline (speedup 1.0000x reference)
#include <cuda_runtime.h>
#include <math.h>

#define BB 4
#define TT 2048
#define CC 512
#define HH 8
#define DD 64
#define BH (BB*HH)
#define MM (BB*TT)
#define EPSV 1e-4f

// ---------------- scratch (static device globals; no allocation) ----------------
__device__ float g_raw[3][MM][CC];          // raw q/k/v projections   (~50 MB)
__device__ float g_sspart[16][3][BB][CC];   // partial column sum-of-squares
__device__ float g_inv[3][BB][CC];          // 1/sqrt(mean+eps) per (w,b,channel)
__device__ float g_qT[BH][DD][TT];          // q normalized*scale, transposed [bh][c][t]
__device__ float g_kT[BH][DD][TT];          // k normalized, transposed
__device__ float g_vn[BH][TT][DD];          // v normalized, [bh][t][d]
__device__ float g_attn[MM][CC];            // attention output in [b,t,C]

// ================= SGEMM 128x128x8, 256 threads, 8x8 microtile =================
__global__ __launch_bounds__(256) void gemm_qkv_kernel(
    const float* __restrict__ A,
    const float* __restrict__ Wq,
    const float* __restrict__ Wk,
    const float* __restrict__ Wv)
{
    const float* Bw = (blockIdx.z == 0) ? Wq : ((blockIdx.z == 1) ? Wk : Wv);
    float* Cout = &g_raw[blockIdx.z][0][0];

    __shared__ float As[8][128];
    __shared__ float Bs[8][128];

    int tid  = threadIdx.x;
    int arow = tid >> 1, acol = (tid & 1) * 4;
    int brow = tid >> 5, bcol = (tid & 31) * 4;
    int tx = tid & 15, ty = tid >> 4;

    const float* Ap = A  + (blockIdx.x * 128 + arow) * CC + acol;
    const float* Bp = Bw + brow * CC + blockIdx.y * 128 + bcol;

    float acc[8][8];
#pragma unroll
    for (int i = 0; i < 8; i++)
#pragma unroll
        for (int j = 0; j < 8; j++) acc[i][j] = 0.f;

    for (int k0 = 0; k0 < CC; k0 += 8) {
        float4 av = *(const float4*)(Ap + k0);
        float4 bv = *(const float4*)(Bp + k0 * CC);
        __syncthreads();
        As[acol + 0][arow] = av.x;
        As[acol + 1][arow] = av.y;
        As[acol + 2][arow] = av.z;
        As[acol + 3][arow] = av.w;
        *(float4*)&Bs[brow][bcol] = bv;
        __syncthreads();
#pragma unroll
        for (int k = 0; k < 8; k++) {
            float a[8], b[8];
            *(float4*)&a[0] = *(const float4*)&As[k][ty * 4];
            *(float4*)&a[4] = *(const float4*)&As[k][ty * 4 + 64];
            *(float4*)&b[0] = *(const float4*)&Bs[k][tx * 4];
            *(float4*)&b[4] = *(const float4*)&Bs[k][tx * 4 + 64];
#pragma unroll
            for (int i = 0; i < 8; i++)
#pragma unroll
                for (int j = 0; j < 8; j++) acc[i][j] += a[i] * b[j];
        }
    }

    int mbase = blockIdx.x * 128, nbase = blockIdx.y * 128;
#pragma unroll
    for (int i = 0; i < 8; i++) {
        int m = mbase + ((i < 4) ? (ty * 4 + i) : (64 + ty * 4 + (i - 4)));
        float4 v0 = make_float4(acc[i][0], acc[i][1], acc[i][2], acc[i][3]);
        float4 v1 = make_float4(acc[i][4], acc[i][5], acc[i][6], acc[i][7]);
        *(float4*)&Cout[m * CC + nbase + tx * 4]      = v0;
        *(float4*)&Cout[m * CC + nbase + tx * 4 + 64] = v1;
    }
}

__global__ __launch_bounds__(256) void gemm_out_kernel(
    const float* __restrict__ Wo,
    const float* __restrict__ bo,
    const float* __restrict__ hs,
    float* __restrict__ out)
{
    const float* A = &g_attn[0][0];

    __shared__ float As[8][128];
    __shared__ float Bs[8][128];

    int tid  = threadIdx.x;
    int arow = tid >> 1, acol = (tid & 1) * 4;
    int brow = tid >> 5, bcol = (tid & 31) * 4;
    int tx = tid & 15, ty = tid >> 4;

    const float* Ap = A  + (blockIdx.x * 128 + arow) * CC + acol;
    const float* Bp = Wo + brow * CC + blockIdx.y * 128 + bcol;

    float acc[8][8];
#pragma unroll
    for (int i = 0; i < 8; i++)
#pragma unroll
        for (int j = 0; j < 8; j++) acc[i][j] = 0.f;

    for (int k0 = 0; k0 < CC; k0 += 8) {
        float4 av = *(const float4*)(Ap + k0);
        float4 bv = *(const float4*)(Bp + k0 * CC);
        __syncthreads();
        As[acol + 0][arow] = av.x;
        As[acol + 1][arow] = av.y;
        As[acol + 2][arow] = av.z;
        As[acol + 3][arow] = av.w;
        *(float4*)&Bs[brow][bcol] = bv;
        __syncthreads();
#pragma unroll
        for (int k = 0; k < 8; k++) {
            float a[8], b[8];
            *(float4*)&a[0] = *(const float4*)&As[k][ty * 4];
            *(float4*)&a[4] = *(const float4*)&As[k][ty * 4 + 64];
            *(float4*)&b[0] = *(const float4*)&Bs[k][tx * 4];
            *(float4*)&b[4] = *(const float4*)&Bs[k][tx * 4 + 64];
#pragma unroll
            for (int i = 0; i < 8; i++)
#pragma unroll
                for (int j = 0; j < 8; j++) acc[i][j] += a[i] * b[j];
        }
    }

    int mbase = blockIdx.x * 128, nbase = blockIdx.y * 128;
#pragma unroll
    for (int i = 0; i < 8; i++) {
        int m = mbase + ((i < 4) ? (ty * 4 + i) : (64 + ty * 4 + (i - 4)));
#pragma unroll
        for (int half = 0; half < 2; half++) {
            int n = nbase + tx * 4 + half * 64;
            float4 bv = *(const float4*)&bo[n];
            float4 rv = *(const float4*)&hs[m * CC + n];
            float4 o;
            o.x = acc[i][half * 4 + 0] + bv.x + rv.x;
            o.y = acc[i][half * 4 + 1] + bv.y + rv.y;
            o.z = acc[i][half * 4 + 2] + bv.z + rv.z;
            o.w = acc[i][half * 4 + 3] + bv.w + rv.w;
            *(float4*)&out[m * CC + n] = o;
        }
    }
}

// ================= pixel-norm: column sum-of-squares over tokens =================
__global__ __launch_bounds__(512) void sumsq_kernel()
{
    int c = threadIdx.x;            // 0..511
    int chunk = blockIdx.x;         // 0..15 (T split)
    int b = blockIdx.y;             // 0..3
    int w = blockIdx.z;             // 0..2
    const float* p = &g_raw[w][b * TT + chunk * (TT / 16)][0];
    float s = 0.f;
#pragma unroll 4
    for (int t = 0; t < TT / 16; t++) {
        float x = p[t * CC + c];
        s += x * x;
    }
    g_sspart[chunk][w][b][c] = s;
}

__global__ __launch_bounds__(512) void finalize_inv_kernel()
{
    int c = threadIdx.x;
    int b = blockIdx.x & 3;
    int w = blockIdx.x >> 2;
    float s = 0.f;
#pragma unroll
    for (int ch = 0; ch < 16; ch++) s += g_sspart[ch][w][b][c];
    g_inv[w][b][c] = rsqrtf(s * (1.0f / TT) + EPSV);
}

// ===== normalize + transpose q,k into [bh][c][t]; fold attn scale into q =====
__global__ void transpose_qk_kernel()
{
    __shared__ float tile[32][33];
    int w  = blockIdx.z & 1;        // 0=q, 1=k
    int bh = blockIdx.z >> 1;       // 0..31
    int b = bh >> 3, h = bh & 7;
    int t0 = blockIdx.x * 32;
    int c0 = blockIdx.y * 32;
    int x = threadIdx.x, y = threadIdx.y;

    int cg = h * DD + c0 + x;
    float inv = g_inv[w][b][cg] * ((w == 0) ? 0.125f : 1.0f);  // 1/sqrt(64)=0.125
#pragma unroll
    for (int yy = 0; yy < 4; yy++) {
        int t = t0 + y + yy * 8;
        tile[y + yy * 8][x] = g_raw[w][b * TT + t][cg] * inv;
    }
    __syncthreads();
    float* dst = w ? &g_kT[0][0][0] : &g_qT[0][0][0];
#pragma unroll
    for (int yy = 0; yy < 4; yy++) {
        int c = c0 + y + yy * 8;
        dst[(bh * DD + c) * (long)TT + t0 + x] = tile[x][y + yy * 8];
    }
}

__global__ __launch_bounds__(256) void normalize_v_kernel()
{
    int i = blockIdx.x * 256 + threadIdx.x;   // over bh*T*16 float4s
    int dc4 = (i & 15) * 4;
    int t   = (i >> 4) & (TT - 1);
    int bh  = i >> 15;
    int b = bh >> 3, h = bh & 7;
    float4 v = *(const float4*)&g_raw[2][b * TT + t][h * DD + dc4];
    const float* invp = &g_inv[2][b][h * DD + dc4];
    float4 o = make_float4(v.x * invp[0], v.y * invp[1], v.z * invp[2], v.w * invp[3]);
    *(float4*)&g_vn[bh][t][dc4] = o;
}

// ================= flash attention: BQ=BKV=64, 128 threads, 8x4 microtile =================
#define FLASH_SMEM ((3 * 64 * 64 + 64 * 65) * 4)

__global__ __launch_bounds__(128) void flash_kernel()
{
    extern __shared__ float sm[];
    float* Qs = sm;                 // [c][r]  64*64
    float* Ks = sm + 4096;          // [c][j]  64*64
    float* Vs = sm + 8192;          // [j][d]  64*64
    float* Ps = sm + 12288;         // [j][r]  64*65 (padded)

    int bh = blockIdx.y;
    int b = bh >> 3, h = bh & 7;
    int q0 = blockIdx.x * 64;
    int tid = threadIdx.x;
    int tx = tid & 15, ty = tid >> 4;     // ty 0..7 (8 rows each), tx 0..15 (4 cols each)

    // load Q tile (already transposed & scaled in global)
    {
        const float* qp = &g_qT[bh][0][0];
        for (int i = tid; i < 64 * 16; i += 128) {
            int c = i >> 4, t4 = (i & 15) * 4;
            *(float4*)&Qs[c * 64 + t4] = *(const float4*)&qp[c * TT + q0 + t4];
        }
    }

    float m[8], l[8], O[8][4];
#pragma unroll
    for (int i = 0; i < 8; i++) {
        m[i] = -1e30f; l[i] = 0.f;
        O[i][0] = O[i][1] = O[i][2] = O[i][3] = 0.f;
    }

    for (int kv0 = 0; kv0 < TT; kv0 += 64) {
        __syncthreads();   // prev PV done (and Q loaded, first iter) before overwriting Ks/Vs
        {
            const float* kp = &g_kT[bh][0][0];
            for (int i = tid; i < 64 * 16; i += 128) {
                int c = i >> 4, t4 = (i & 15) * 4;
                *(float4*)&Ks[c * 64 + t4] = *(const float4*)&kp[c * TT + kv0 + t4];
            }
            const float* vp = &g_vn[bh][kv0][0];
            for (int i = tid; i < 64 * 16; i += 128) {
                int j = i >> 4, d4 = (i & 15) * 4;
                *(float4*)&Vs[j * 64 + d4] = *(const float4*)&vp[j * DD + d4];
            }
        }
        __syncthreads();

        // S = Q @ K^T  (scale already folded into Q)
        float S[8][4];
#pragma unroll
        for (int i = 0; i < 8; i++) { S[i][0] = S[i][1] = S[i][2] = S[i][3] = 0.f; }
#pragma unroll 16
        for (int k = 0; k < 64; k++) {
            float a[8], bb[4];
            *(float4*)&a[0]  = *(const float4*)&Qs[k * 64 + ty * 8];
            *(float4*)&a[4]  = *(const float4*)&Qs[k * 64 + ty * 8 + 4];
            *(float4*)&bb[0] = *(const float4*)&Ks[k * 64 + tx * 4];
#pragma unroll
            for (int i = 0; i < 8; i++)
#pragma unroll
                for (int j = 0; j < 4; j++) S[i][j] += a[i] * bb[j];
        }

        // online softmax (row reductions across the 16 tx lanes of this half-warp)
#pragma unroll
        for (int i = 0; i < 8; i++) {
            float tm = fmaxf(fmaxf(S[i][0], S[i][1]), fmaxf(S[i][2], S[i][3]));
            tm = fmaxf(tm, __shfl_xor_sync(0xffffffffu, tm, 1));
            tm = fmaxf(tm, __shfl_xor_sync(0xffffffffu, tm, 2));
            tm = fmaxf(tm, __shfl_xor_sync(0xffffffffu, tm, 4));
            tm = fmaxf(tm, __shfl_xor_sync(0xffffffffu, tm, 8));
            float mn = fmaxf(m[i], tm);
            float corr = __expf(m[i] - mn);
            float rs = 0.f;
#pragma unroll
            for (int j = 0; j < 4; j++) { S[i][j] = __expf(S[i][j] - mn); rs += S[i][j]; }
            rs += __shfl_xor_sync(0xffffffffu, rs, 1);
            rs += __shfl_xor_sync(0xffffffffu, rs, 2);
            rs += __shfl_xor_sync(0xffffffffu, rs, 4);
            rs += __shfl_xor_sync(0xffffffffu, rs, 8);
            l[i] = l[i] * corr + rs;
            m[i] = mn;
#pragma unroll
            for (int j = 0; j < 4; j++) O[i][j] *= corr;
        }

        // store P transposed [j][r] (stride 65 -> only 2-way store conflicts)
#pragma unroll
        for (int i = 0; i < 8; i++)
#pragma unroll
            for (int j = 0; j < 4; j++)
                Ps[(tx * 4 + j) * 65 + ty * 8 + i] = S[i][j];
        __syncthreads();

        // O += P @ V
#pragma unroll 16
        for (int k = 0; k < 64; k++) {
            float a[8];
#pragma unroll
            for (int i = 0; i < 8; i++) a[i] = Ps[k * 65 + ty * 8 + i];
            float4 bv = *(const float4*)&Vs[k * 64 + tx * 4];
#pragma unroll
            for (int i = 0; i < 8; i++) {
                O[i][0] += a[i] * bv.x;
                O[i][1] += a[i] * bv.y;
                O[i][2] += a[i] * bv.z;
                O[i][3] += a[i] * bv.w;
            }
        }
    }

    // epilogue: divide by l, write [b,t,C]
#pragma unroll
    for (int i = 0; i < 8; i++) {
        float linv = 1.0f / l[i];
        int row = q0 + ty * 8 + i;
        float4 o = make_float4(O[i][0] * linv, O[i][1] * linv, O[i][2] * linv, O[i][3] * linv);
        *(float4*)&g_attn[b * TT + row][h * DD + tx * 4] = o;
    }
}

// ======================================================================
extern "C" void kernel_launch(void* const* d_in, const int* in_sizes, int n_in,
                              void* d_out, int out_size)
{
    const float* hs = (const float*)d_in[0];
    const float* Wq = (const float*)d_in[1];
    const float* Wk = (const float*)d_in[2];
    const float* Wv = (const float*)d_in[3];
    const float* Wo = (const float*)d_in[4];
    const float* bo = (const float*)d_in[5];
    float* out = (float*)d_out;

    // 1) q/k/v projections
    gemm_qkv_kernel<<<dim3(64, 4, 3), 256>>>(hs, Wq, Wk, Wv);
    // 2) pixel-norm stats (over token axis)
    sumsq_kernel<<<dim3(16, 4, 3), 512>>>();
    finalize_inv_kernel<<<12, 512>>>();
    // 3) normalize + transpose q,k (fold 1/sqrt(d) into q); normalize v
    transpose_qk_kernel<<<dim3(64, 2, 64), dim3(32, 8)>>>();
    normalize_v_kernel<<<4096, 256>>>();
    // 4) flash attention
    cudaFuncSetAttribute(flash_kernel, cudaFuncAttributeMaxDynamicSharedMemorySize, FLASH_SMEM);
    flash_kernel<<<dim3(32, 32), 128, FLASH_SMEM>>>();
    // 5) output projection + bias + residual
    gemm_out_kernel<<<dim3(64, 4), 256>>>(Wo, bo, hs, out);
}

// round 5
// speedup vs baseline: 2.0932x; 2.0932x over previous
#include <cuda_runtime.h>
#include <cuda_fp16.h>
#include <stdint.h>
#include <math.h>

#define BB 4
#define TT 2048
#define CC 512
#define HH 8
#define DD 64
#define BH (BB*HH)
#define MM (BB*TT)
#define EPSV 1e-4f

typedef unsigned int u32;

// ---------------- scratch (static device globals; no allocation) ----------------
__device__ float g_raw[3][MM][CC];          // raw q/k/v projections
__device__ float g_sspart[16][3][BB][CC];   // partial column sum-of-squares
__device__ float g_inv[3][BB][CC];          // 1/sqrt(mean+eps) per (w,b,channel)
__device__ __half g_qn[BH][TT][DD];         // normalized q (attn scale folded), fp16
__device__ __half g_kn[BH][TT][DD];         // normalized k, fp16
__device__ __half g_vn[BH][TT][DD];         // normalized v, fp16
__device__ float g_attn[MM][CC];            // attention output [b,t,C] fp32

// ================= SGEMM 128x128x8, 256 threads, 8x8 microtile =================
__global__ __launch_bounds__(256) void gemm_qkv_kernel(
    const float* __restrict__ A,
    const float* __restrict__ Wq,
    const float* __restrict__ Wk,
    const float* __restrict__ Wv)
{
    const float* Bw = (blockIdx.z == 0) ? Wq : ((blockIdx.z == 1) ? Wk : Wv);
    float* Cout = &g_raw[blockIdx.z][0][0];

    __shared__ float As[8][128];
    __shared__ float Bs[8][128];

    int tid  = threadIdx.x;
    int arow = tid >> 1, acol = (tid & 1) * 4;
    int brow = tid >> 5, bcol = (tid & 31) * 4;
    int tx = tid & 15, ty = tid >> 4;

    const float* Ap = A  + (blockIdx.x * 128 + arow) * CC + acol;
    const float* Bp = Bw + brow * CC + blockIdx.y * 128 + bcol;

    float acc[8][8];
#pragma unroll
    for (int i = 0; i < 8; i++)
#pragma unroll
        for (int j = 0; j < 8; j++) acc[i][j] = 0.f;

    for (int k0 = 0; k0 < CC; k0 += 8) {
        float4 av = *(const float4*)(Ap + k0);
        float4 bv = *(const float4*)(Bp + k0 * CC);
        __syncthreads();
        As[acol + 0][arow] = av.x;
        As[acol + 1][arow] = av.y;
        As[acol + 2][arow] = av.z;
        As[acol + 3][arow] = av.w;
        *(float4*)&Bs[brow][bcol] = bv;
        __syncthreads();
#pragma unroll
        for (int k = 0; k < 8; k++) {
            float a[8], b[8];
            *(float4*)&a[0] = *(const float4*)&As[k][ty * 4];
            *(float4*)&a[4] = *(const float4*)&As[k][ty * 4 + 64];
            *(float4*)&b[0] = *(const float4*)&Bs[k][tx * 4];
            *(float4*)&b[4] = *(const float4*)&Bs[k][tx * 4 + 64];
#pragma unroll
            for (int i = 0; i < 8; i++)
#pragma unroll
                for (int j = 0; j < 8; j++) acc[i][j] += a[i] * b[j];
        }
    }

    int mbase = blockIdx.x * 128, nbase = blockIdx.y * 128;
#pragma unroll
    for (int i = 0; i < 8; i++) {
        int m = mbase + ((i < 4) ? (ty * 4 + i) : (64 + ty * 4 + (i - 4)));
        float4 v0 = make_float4(acc[i][0], acc[i][1], acc[i][2], acc[i][3]);
        float4 v1 = make_float4(acc[i][4], acc[i][5], acc[i][6], acc[i][7]);
        *(float4*)&Cout[m * CC + nbase + tx * 4]      = v0;
        *(float4*)&Cout[m * CC + nbase + tx * 4 + 64] = v1;
    }
}

__global__ __launch_bounds__(256) void gemm_out_kernel(
    const float* __restrict__ Wo,
    const float* __restrict__ bo,
    const float* __restrict__ hs,
    float* __restrict__ out)
{
    const float* A = &g_attn[0][0];

    __shared__ float As[8][128];
    __shared__ float Bs[8][128];

    int tid  = threadIdx.x;
    int arow = tid >> 1, acol = (tid & 1) * 4;
    int brow = tid >> 5, bcol = (tid & 31) * 4;
    int tx = tid & 15, ty = tid >> 4;

    const float* Ap = A  + (blockIdx.x * 128 + arow) * CC + acol;
    const float* Bp = Wo + brow * CC + blockIdx.y * 128 + bcol;

    float acc[8][8];
#pragma unroll
    for (int i = 0; i < 8; i++)
#pragma unroll
        for (int j = 0; j < 8; j++) acc[i][j] = 0.f;

    for (int k0 = 0; k0 < CC; k0 += 8) {
        float4 av = *(const float4*)(Ap + k0);
        float4 bv = *(const float4*)(Bp + k0 * CC);
        __syncthreads();
        As[acol + 0][arow] = av.x;
        As[acol + 1][arow] = av.y;
        As[acol + 2][arow] = av.z;
        As[acol + 3][arow] = av.w;
        *(float4*)&Bs[brow][bcol] = bv;
        __syncthreads();
#pragma unroll
        for (int k = 0; k < 8; k++) {
            float a[8], b[8];
            *(float4*)&a[0] = *(const float4*)&As[k][ty * 4];
            *(float4*)&a[4] = *(const float4*)&As[k][ty * 4 + 64];
            *(float4*)&b[0] = *(const float4*)&Bs[k][tx * 4];
            *(float4*)&b[4] = *(const float4*)&Bs[k][tx * 4 + 64];
#pragma unroll
            for (int i = 0; i < 8; i++)
#pragma unroll
                for (int j = 0; j < 8; j++) acc[i][j] += a[i] * b[j];
        }
    }

    int mbase = blockIdx.x * 128, nbase = blockIdx.y * 128;
#pragma unroll
    for (int i = 0; i < 8; i++) {
        int m = mbase + ((i < 4) ? (ty * 4 + i) : (64 + ty * 4 + (i - 4)));
#pragma unroll
        for (int half = 0; half < 2; half++) {
            int n = nbase + tx * 4 + half * 64;
            float4 bv = *(const float4*)&bo[n];
            float4 rv = *(const float4*)&hs[m * CC + n];
            float4 o;
            o.x = acc[i][half * 4 + 0] + bv.x + rv.x;
            o.y = acc[i][half * 4 + 1] + bv.y + rv.y;
            o.z = acc[i][half * 4 + 2] + bv.z + rv.z;
            o.w = acc[i][half * 4 + 3] + bv.w + rv.w;
            *(float4*)&out[m * CC + n] = o;
        }
    }
}

// ================= pixel-norm: column sum-of-squares over tokens =================
__global__ __launch_bounds__(512) void sumsq_kernel()
{
    int c = threadIdx.x;
    int chunk = blockIdx.x;
    int b = blockIdx.y;
    int w = blockIdx.z;
    const float* p = &g_raw[w][b * TT + chunk * (TT / 16)][0];
    float s = 0.f;
#pragma unroll 4
    for (int t = 0; t < TT / 16; t++) {
        float x = p[t * CC + c];
        s += x * x;
    }
    g_sspart[chunk][w][b][c] = s;
}

__global__ __launch_bounds__(512) void finalize_inv_kernel()
{
    int c = threadIdx.x;
    int b = blockIdx.x & 3;
    int w = blockIdx.x >> 2;
    float s = 0.f;
#pragma unroll
    for (int ch = 0; ch < 16; ch++) s += g_sspart[ch][w][b][c];
    g_inv[w][b][c] = rsqrtf(s * (1.0f / TT) + EPSV);
}

// ===== normalize q,k,v -> fp16 [bh][t][d]; fold 1/sqrt(d) into q =====
__global__ __launch_bounds__(256) void normalize_kernel()
{
    int i = blockIdx.x * 256 + threadIdx.x;   // over 3*32*2048*8 chunks of 8 elems
    int c8 = (i & 7) * 8;
    int t  = (i >> 3) & (TT - 1);
    int bh = (i >> 14) & 31;
    int w  = i >> 19;
    int b = bh >> 3, h = bh & 7;
    int cg = h * DD + c8;

    float4 v0 = *(const float4*)&g_raw[w][b * TT + t][cg];
    float4 v1 = *(const float4*)&g_raw[w][b * TT + t][cg + 4];
    const float* ip = &g_inv[w][b][cg];
    float sc = (w == 0) ? 0.125f : 1.0f;   // 1/sqrt(64)

    __align__(16) __half2 o[4];
    o[0] = __floats2half2_rn(v0.x * ip[0] * sc, v0.y * ip[1] * sc);
    o[1] = __floats2half2_rn(v0.z * ip[2] * sc, v0.w * ip[3] * sc);
    o[2] = __floats2half2_rn(v1.x * ip[4] * sc, v1.y * ip[5] * sc);
    o[3] = __floats2half2_rn(v1.z * ip[6] * sc, v1.w * ip[7] * sc);

    __half* dst = (w == 0) ? &g_qn[0][0][0] : ((w == 1) ? &g_kn[0][0][0] : &g_vn[0][0][0]);
    *(uint4*)&dst[(bh * TT + t) * DD + c8] = *(uint4*)o;
}

// ================= flash attention: mma.sync fp16, BQ=BKV=64, 4 warps =================
#define QSTR 72   // padded row stride (halfs)

__device__ __forceinline__ void mma16816(float* c, const u32* a, const u32* b)
{
    asm volatile(
        "mma.sync.aligned.m16n8k16.row.col.f32.f16.f16.f32 "
        "{%0,%1,%2,%3}, {%4,%5,%6,%7}, {%8,%9}, {%0,%1,%2,%3};"
        : "+f"(c[0]), "+f"(c[1]), "+f"(c[2]), "+f"(c[3])
        : "r"(a[0]), "r"(a[1]), "r"(a[2]), "r"(a[3]), "r"(b[0]), "r"(b[1]));
}

__device__ __forceinline__ void ldsm4(u32* r, u32 addr)
{
    asm volatile("ldmatrix.sync.aligned.m8n8.x4.shared.b16 {%0,%1,%2,%3}, [%4];"
                 : "=r"(r[0]), "=r"(r[1]), "=r"(r[2]), "=r"(r[3]) : "r"(addr));
}

__device__ __forceinline__ void ldsm4t(u32* r, u32 addr)
{
    asm volatile("ldmatrix.sync.aligned.m8n8.x4.trans.shared.b16 {%0,%1,%2,%3}, [%4];"
                 : "=r"(r[0]), "=r"(r[1]), "=r"(r[2]), "=r"(r[3]) : "r"(addr));
}

__device__ __forceinline__ u32 pack_half2(float lo, float hi)
{
    u32 d;
    asm("cvt.rn.f16x2.f32 %0, %1, %2;" : "=r"(d) : "f"(hi), "f"(lo));
    return d;
}

__device__ __forceinline__ float qmax(float v)
{
    v = fmaxf(v, __shfl_xor_sync(0xffffffffu, v, 1));
    v = fmaxf(v, __shfl_xor_sync(0xffffffffu, v, 2));
    return v;
}

__device__ __forceinline__ float qsum(float v)
{
    v += __shfl_xor_sync(0xffffffffu, v, 1);
    v += __shfl_xor_sync(0xffffffffu, v, 2);
    return v;
}

__global__ __launch_bounds__(128) void flash_kernel()
{
    __shared__ __align__(16) __half Qs[64 * QSTR];
    __shared__ __align__(16) __half Ks[64 * QSTR];
    __shared__ __align__(16) __half Vs[64 * QSTR];

    int bh = blockIdx.y;
    int b = bh >> 3, h = bh & 7;
    int q0 = blockIdx.x * 64;
    int tid = threadIdx.x;
    int lane = tid & 31, wrp = tid >> 5;
    int grp = lane >> 2, tig = lane & 3;

    u32 qb = (u32)__cvta_generic_to_shared(Qs);
    u32 kb = (u32)__cvta_generic_to_shared(Ks);
    u32 vb = (u32)__cvta_generic_to_shared(Vs);

    // ---- stage Q tile, load Q fragments into registers (kept for whole loop) ----
    {
        const __half* qg = &g_qn[bh][q0][0];
        for (int i = tid; i < 64 * 8; i += 128) {
            int r = i >> 3, c8 = (i & 7) * 8;
            *(uint4*)&Qs[r * QSTR + c8] = *(const uint4*)&qg[r * DD + c8];
        }
    }
    __syncthreads();

    u32 Aq[4][4];
#pragma unroll
    for (int kk = 0; kk < 4; kk++) {
        int row = wrp * 16 + (lane & 15);
        int col = kk * 16 + (lane >> 4) * 8;
        ldsm4(Aq[kk], qb + (u32)(row * QSTR + col) * 2u);
    }

    float m_lo = -1e30f, m_hi = -1e30f, l_lo = 0.f, l_hi = 0.f;
    float O[8][4];
#pragma unroll
    for (int dt = 0; dt < 8; dt++) {
        O[dt][0] = 0.f; O[dt][1] = 0.f; O[dt][2] = 0.f; O[dt][3] = 0.f;
    }

    for (int kv0 = 0; kv0 < TT; kv0 += 64) {
        __syncthreads();   // previous iter's ldsm reads done before overwrite
        {
            const __half* kg = &g_kn[bh][kv0][0];
            const __half* vg = &g_vn[bh][kv0][0];
            for (int i = tid; i < 64 * 8; i += 128) {
                int r = i >> 3, c8 = (i & 7) * 8;
                *(uint4*)&Ks[r * QSTR + c8] = *(const uint4*)&kg[r * DD + c8];
                *(uint4*)&Vs[r * QSTR + c8] = *(const uint4*)&vg[r * DD + c8];
            }
        }
        __syncthreads();

        // ---- S = Q @ K^T (scale already folded into Q) ----
        float S[8][4];
#pragma unroll
        for (int jt = 0; jt < 8; jt++) {
            S[jt][0] = 0.f; S[jt][1] = 0.f; S[jt][2] = 0.f; S[jt][3] = 0.f;
        }
#pragma unroll
        for (int kk = 0; kk < 4; kk++) {
            u32 Bk[8][2];
#pragma unroll
            for (int p = 0; p < 4; p++) {
                int row = p * 16 + (lane & 7) + ((lane & 16) ? 8 : 0);
                int col = kk * 16 + ((lane & 8) ? 8 : 0);
                u32 r4[4];
                ldsm4(r4, kb + (u32)(row * QSTR + col) * 2u);
                Bk[2 * p][0] = r4[0]; Bk[2 * p][1] = r4[1];
                Bk[2 * p + 1][0] = r4[2]; Bk[2 * p + 1][1] = r4[3];
            }
#pragma unroll
            for (int jt = 0; jt < 8; jt++) mma16816(S[jt], Aq[kk], Bk[jt]);
        }

        // ---- online softmax (rows grp and grp+8; reduce across the quad) ----
        float mx_lo = -1e30f, mx_hi = -1e30f;
#pragma unroll
        for (int jt = 0; jt < 8; jt++) {
            mx_lo = fmaxf(mx_lo, fmaxf(S[jt][0], S[jt][1]));
            mx_hi = fmaxf(mx_hi, fmaxf(S[jt][2], S[jt][3]));
        }
        mx_lo = qmax(mx_lo);
        mx_hi = qmax(mx_hi);

        float mn_lo = fmaxf(m_lo, mx_lo);
        float mn_hi = fmaxf(m_hi, mx_hi);
        float corr_lo = __expf(m_lo - mn_lo);
        float corr_hi = __expf(m_hi - mn_hi);
        m_lo = mn_lo;
        m_hi = mn_hi;

        float rs_lo = 0.f, rs_hi = 0.f;
#pragma unroll
        for (int jt = 0; jt < 8; jt++) {
            S[jt][0] = __expf(S[jt][0] - m_lo);
            S[jt][1] = __expf(S[jt][1] - m_lo);
            S[jt][2] = __expf(S[jt][2] - m_hi);
            S[jt][3] = __expf(S[jt][3] - m_hi);
            rs_lo += S[jt][0] + S[jt][1];
            rs_hi += S[jt][2] + S[jt][3];
        }
        rs_lo = qsum(rs_lo);
        rs_hi = qsum(rs_hi);
        l_lo = l_lo * corr_lo + rs_lo;
        l_hi = l_hi * corr_hi + rs_hi;

#pragma unroll
        for (int dt = 0; dt < 8; dt++) {
            O[dt][0] *= corr_lo; O[dt][1] *= corr_lo;
            O[dt][2] *= corr_hi; O[dt][3] *= corr_hi;
        }

        // ---- O += P @ V  (P a-frags built in registers from S c-frags) ----
#pragma unroll
        for (int kk = 0; kk < 4; kk++) {
            u32 Pa[4];
            Pa[0] = pack_half2(S[2 * kk][0],     S[2 * kk][1]);
            Pa[1] = pack_half2(S[2 * kk][2],     S[2 * kk][3]);
            Pa[2] = pack_half2(S[2 * kk + 1][0], S[2 * kk + 1][1]);
            Pa[3] = pack_half2(S[2 * kk + 1][2], S[2 * kk + 1][3]);
#pragma unroll
            for (int p = 0; p < 4; p++) {
                int row = kk * 16 + (lane & 15);      // j (k-dim)
                int col = p * 16 + (lane >> 4) * 8;   // d (n-dim)
                u32 r4[4];
                ldsm4t(r4, vb + (u32)(row * QSTR + col) * 2u);
                u32 Bv0[2]; Bv0[0] = r4[0]; Bv0[1] = r4[1];
                u32 Bv1[2]; Bv1[0] = r4[2]; Bv1[1] = r4[3];
                mma16816(O[2 * p],     Pa, Bv0);
                mma16816(O[2 * p + 1], Pa, Bv1);
            }
        }
    }

    // ---- epilogue: divide by l, write [b,t,C] fp32 ----
    float il_lo = 1.0f / l_lo;
    float il_hi = 1.0f / l_hi;
    int r_lo = q0 + wrp * 16 + grp;
    int r_hi = r_lo + 8;
#pragma unroll
    for (int dt = 0; dt < 8; dt++) {
        int col = h * DD + dt * 8 + 2 * tig;
        float2 o0 = make_float2(O[dt][0] * il_lo, O[dt][1] * il_lo);
        float2 o1 = make_float2(O[dt][2] * il_hi, O[dt][3] * il_hi);
        *(float2*)&g_attn[b * TT + r_lo][col] = o0;
        *(float2*)&g_attn[b * TT + r_hi][col] = o1;
    }
}

// ======================================================================
extern "C" void kernel_launch(void* const* d_in, const int* in_sizes, int n_in,
                              void* d_out, int out_size)
{
    const float* hs = (const float*)d_in[0];
    const float* Wq = (const float*)d_in[1];
    const float* Wk = (const float*)d_in[2];
    const float* Wv = (const float*)d_in[3];
    const float* Wo = (const float*)d_in[4];
    const float* bo = (const float*)d_in[5];
    float* out = (float*)d_out;

    // 1) q/k/v projections (fp32 SIMT)
    gemm_qkv_kernel<<<dim3(64, 4, 3), 256>>>(hs, Wq, Wk, Wv);
    // 2) pixel-norm stats (over token axis)
    sumsq_kernel<<<dim3(16, 4, 3), 512>>>();
    finalize_inv_kernel<<<12, 512>>>();
    // 3) normalize + convert to fp16 [bh][t][d] (fold 1/sqrt(d) into q)
    normalize_kernel<<<6144, 256>>>();
    // 4) flash attention on tensor cores (fp16 mma.sync)
    flash_kernel<<<dim3(32, 32), 128>>>();
    // 5) output projection + bias + residual (fp32 SIMT)
    gemm_out_kernel<<<dim3(64, 4), 256>>>(Wo, bo, hs, out);
}

// round 6
// speedup vs baseline: 4.5716x; 2.1840x over previous
#include <cuda_runtime.h>
#include <cuda_fp16.h>
#include <stdint.h>
#include <math.h>

#define BB 4
#define TT 2048
#define CC 512
#define HH 8
#define DD 64
#define BH (BB*HH)
#define MM (BB*TT)
#define EPSV 1e-4f

typedef unsigned int u32;

// ---------------- scratch (static device globals; no allocation) ----------------
__device__ __half g_hs16[MM][CC];           // hidden states fp16
__device__ __half g_w16[4][CC][CC];         // Wq,Wk,Wv,Wo fp16
__device__ __half g_raw16[3][MM][CC];       // raw q/k/v projections fp16
__device__ __half g_nrm16[3][MM][CC];       // normalized q/k/v fp16 (scale folded into q)
__device__ __half g_attn16[MM][CC];         // attention output fp16
__device__ float g_sspart[16][3][BB][CC];   // partial column sum-of-squares
__device__ float g_inv[3][BB][CC];          // 1/sqrt(mean+eps) per (w,b,channel)

// ---------------- mma/ldmatrix primitives ----------------
__device__ __forceinline__ void mma16816(float* c, const u32* a, const u32* b)
{
    asm volatile(
        "mma.sync.aligned.m16n8k16.row.col.f32.f16.f16.f32 "
        "{%0,%1,%2,%3}, {%4,%5,%6,%7}, {%8,%9}, {%0,%1,%2,%3};"
        : "+f"(c[0]), "+f"(c[1]), "+f"(c[2]), "+f"(c[3])
        : "r"(a[0]), "r"(a[1]), "r"(a[2]), "r"(a[3]), "r"(b[0]), "r"(b[1]));
}

__device__ __forceinline__ void ldsm4(u32* r, u32 addr)
{
    asm volatile("ldmatrix.sync.aligned.m8n8.x4.shared.b16 {%0,%1,%2,%3}, [%4];"
                 : "=r"(r[0]), "=r"(r[1]), "=r"(r[2]), "=r"(r[3]) : "r"(addr));
}

__device__ __forceinline__ void ldsm4t(u32* r, u32 addr)
{
    asm volatile("ldmatrix.sync.aligned.m8n8.x4.trans.shared.b16 {%0,%1,%2,%3}, [%4];"
                 : "=r"(r[0]), "=r"(r[1]), "=r"(r[2]), "=r"(r[3]) : "r"(addr));
}

__device__ __forceinline__ u32 pack_half2(float lo, float hi)
{
    u32 d;
    asm("cvt.rn.f16x2.f32 %0, %1, %2;" : "=r"(d) : "f"(hi), "f"(lo));
    return d;
}

__device__ __forceinline__ float qmax(float v)
{
    v = fmaxf(v, __shfl_xor_sync(0xffffffffu, v, 1));
    v = fmaxf(v, __shfl_xor_sync(0xffffffffu, v, 2));
    return v;
}

__device__ __forceinline__ float qsum(float v)
{
    v += __shfl_xor_sync(0xffffffffu, v, 1);
    v += __shfl_xor_sync(0xffffffffu, v, 2);
    return v;
}

// ---------------- fp32 -> fp16 bulk convert ----------------
__global__ __launch_bounds__(256) void f2h_kernel(const float* __restrict__ src,
                                                  __half* __restrict__ dst, int n)
{
    int i = (blockIdx.x * 256 + threadIdx.x) * 8;
    if (i >= n) return;
    float4 a = *(const float4*)(src + i);
    float4 b = *(const float4*)(src + i + 4);
    __align__(16) __half2 o[4];
    o[0] = __floats2half2_rn(a.x, a.y);
    o[1] = __floats2half2_rn(a.z, a.w);
    o[2] = __floats2half2_rn(b.x, b.y);
    o[3] = __floats2half2_rn(b.z, b.w);
    *(uint4*)(dst + i) = *(uint4*)o;
}

// ================= fp16 tensor-core GEMM: 128x128 tile, K-step 64, 256 thr =================
// A [M x 512] row-major fp16, B [512 x 512] row-major (k-major) fp16; B frags via ldmatrix.trans
#define ASTR 72
#define BSTR 136

struct GemmAcc { float a[2][8][4]; };

__device__ __forceinline__ void gemm16_core(const __half* __restrict__ A,
                                            const __half* __restrict__ Bw,
                                            int bm0, int bn0,
                                            __half* As, __half* Bs,
                                            GemmAcc& acc)
{
    int tid = threadIdx.x;
    int lane = tid & 31, wrp = tid >> 5;
    int wm = wrp & 3, wn = wrp >> 2;

    u32 as_b = (u32)__cvta_generic_to_shared(As);
    u32 bs_b = (u32)__cvta_generic_to_shared(Bs);

#pragma unroll
    for (int mt = 0; mt < 2; mt++)
#pragma unroll
        for (int nt = 0; nt < 8; nt++) {
            acc.a[mt][nt][0] = 0.f; acc.a[mt][nt][1] = 0.f;
            acc.a[mt][nt][2] = 0.f; acc.a[mt][nt][3] = 0.f;
        }

    uint4 ra[4], rb[4];
    // preload k0 = 0
#pragma unroll
    for (int p = 0; p < 4; p++) {
        int idx = p * 256 + tid;
        int r = idx >> 3, c8 = (idx & 7) * 8;
        ra[p] = *(const uint4*)&A[(bm0 + r) * CC + c8];
    }
#pragma unroll
    for (int p = 0; p < 4; p++) {
        int idx = p * 256 + tid;
        int r = idx >> 4, c8 = (idx & 15) * 8;
        rb[p] = *(const uint4*)&Bw[r * CC + bn0 + c8];
    }

    for (int it = 0; it < 8; it++) {
        __syncthreads();
#pragma unroll
        for (int p = 0; p < 4; p++) {
            int idx = p * 256 + tid;
            int r = idx >> 3, c8 = (idx & 7) * 8;
            *(uint4*)&As[r * ASTR + c8] = ra[p];
        }
#pragma unroll
        for (int p = 0; p < 4; p++) {
            int idx = p * 256 + tid;
            int r = idx >> 4, c8 = (idx & 15) * 8;
            *(uint4*)&Bs[r * BSTR + c8] = rb[p];
        }
        __syncthreads();

        if (it < 7) {
            int k0 = (it + 1) * 64;
#pragma unroll
            for (int p = 0; p < 4; p++) {
                int idx = p * 256 + tid;
                int r = idx >> 3, c8 = (idx & 7) * 8;
                ra[p] = *(const uint4*)&A[(bm0 + r) * CC + k0 + c8];
            }
#pragma unroll
            for (int p = 0; p < 4; p++) {
                int idx = p * 256 + tid;
                int r = idx >> 4, c8 = (idx & 15) * 8;
                rb[p] = *(const uint4*)&Bw[(k0 + r) * CC + bn0 + c8];
            }
        }

#pragma unroll
        for (int kk = 0; kk < 4; kk++) {
            u32 Af[2][4];
#pragma unroll
            for (int mt = 0; mt < 2; mt++) {
                int row = wm * 32 + mt * 16 + (lane & 15);
                int col = kk * 16 + (lane >> 4) * 8;
                ldsm4(Af[mt], as_b + (u32)(row * ASTR + col) * 2u);
            }
            u32 Bf[8][2];
#pragma unroll
            for (int p = 0; p < 4; p++) {
                int row = kk * 16 + (lane & 15);
                int col = wn * 64 + p * 16 + (lane >> 4) * 8;
                u32 r4[4];
                ldsm4t(r4, bs_b + (u32)(row * BSTR + col) * 2u);
                Bf[2 * p][0] = r4[0]; Bf[2 * p][1] = r4[1];
                Bf[2 * p + 1][0] = r4[2]; Bf[2 * p + 1][1] = r4[3];
            }
#pragma unroll
            for (int mt = 0; mt < 2; mt++)
#pragma unroll
                for (int nt = 0; nt < 8; nt++)
                    mma16816(acc.a[mt][nt], Af[mt], Bf[nt]);
        }
    }
}

__global__ __launch_bounds__(256) void gemm16_qkv_kernel()
{
    __shared__ __align__(16) __half As[128 * ASTR];
    __shared__ __align__(16) __half Bs[64 * BSTR];

    int w = blockIdx.z;
    int bm0 = blockIdx.x * 128, bn0 = blockIdx.y * 128;
    const __half* A = &g_hs16[0][0];
    const __half* Bw = &g_w16[w][0][0];
    __half* Cout = &g_raw16[w][0][0];

    GemmAcc acc;
    gemm16_core(A, Bw, bm0, bn0, As, Bs, acc);

    int tid = threadIdx.x;
    int lane = tid & 31, wrp = tid >> 5;
    int wm = wrp & 3, wn = wrp >> 2;
    int grp = lane >> 2, tig = lane & 3;

#pragma unroll
    for (int mt = 0; mt < 2; mt++)
#pragma unroll
        for (int nt = 0; nt < 8; nt++) {
            int m = bm0 + wm * 32 + mt * 16 + grp;
            int n = bn0 + wn * 64 + nt * 8 + 2 * tig;
            *(__half2*)&Cout[m * CC + n] =
                __floats2half2_rn(acc.a[mt][nt][0], acc.a[mt][nt][1]);
            *(__half2*)&Cout[(m + 8) * CC + n] =
                __floats2half2_rn(acc.a[mt][nt][2], acc.a[mt][nt][3]);
        }
}

__global__ __launch_bounds__(256) void gemm16_out_kernel(
    const float* __restrict__ bo,
    const float* __restrict__ hs,
    float* __restrict__ out)
{
    __shared__ __align__(16) __half As[128 * ASTR];
    __shared__ __align__(16) __half Bs[64 * BSTR];

    int bm0 = blockIdx.x * 128, bn0 = blockIdx.y * 128;
    const __half* A = &g_attn16[0][0];
    const __half* Bw = &g_w16[3][0][0];

    GemmAcc acc;
    gemm16_core(A, Bw, bm0, bn0, As, Bs, acc);

    int tid = threadIdx.x;
    int lane = tid & 31, wrp = tid >> 5;
    int wm = wrp & 3, wn = wrp >> 2;
    int grp = lane >> 2, tig = lane & 3;

#pragma unroll
    for (int mt = 0; mt < 2; mt++)
#pragma unroll
        for (int nt = 0; nt < 8; nt++) {
            int m = bm0 + wm * 32 + mt * 16 + grp;
            int n = bn0 + wn * 64 + nt * 8 + 2 * tig;
            float2 bv = *(const float2*)&bo[n];
            float2 r0 = *(const float2*)&hs[m * CC + n];
            float2 r1 = *(const float2*)&hs[(m + 8) * CC + n];
            float2 o0 = make_float2(acc.a[mt][nt][0] + bv.x + r0.x,
                                    acc.a[mt][nt][1] + bv.y + r0.y);
            float2 o1 = make_float2(acc.a[mt][nt][2] + bv.x + r1.x,
                                    acc.a[mt][nt][3] + bv.y + r1.y);
            *(float2*)&out[m * CC + n] = o0;
            *(float2*)&out[(m + 8) * CC + n] = o1;
        }
}

// ================= pixel-norm: column sum-of-squares over tokens (fp16 in) =================
__global__ __launch_bounds__(512) void sumsq_kernel()
{
    int c = threadIdx.x;
    int chunk = blockIdx.x;
    int b = blockIdx.y;
    int w = blockIdx.z;
    const __half* p = &g_raw16[w][b * TT + chunk * (TT / 16)][0];
    float s = 0.f;
#pragma unroll 4
    for (int t = 0; t < TT / 16; t++) {
        float x = __half2float(p[t * CC + c]);
        s += x * x;
    }
    g_sspart[chunk][w][b][c] = s;
}

__global__ __launch_bounds__(512) void finalize_inv_kernel()
{
    int c = threadIdx.x;
    int b = blockIdx.x & 3;
    int w = blockIdx.x >> 2;
    float s = 0.f;
#pragma unroll
    for (int ch = 0; ch < 16; ch++) s += g_sspart[ch][w][b][c];
    g_inv[w][b][c] = rsqrtf(s * (1.0f / TT) + EPSV);
}

// ===== normalize q,k,v (fp16 -> fp16, same [b,t,C] layout); fold 1/sqrt(d) into q =====
__global__ __launch_bounds__(256) void normalize_kernel()
{
    int i = blockIdx.x * 256 + threadIdx.x;   // 3 * 8192 * 64 work items
    int c8 = (i & 63) * 8;
    int m  = (i >> 6) & (MM - 1);
    int w  = i >> 19;
    int b  = m >> 11;

    uint4 raw = *(const uint4*)&g_raw16[w][m][c8];
    __half2* hp = (__half2*)&raw;
    const float* ip = &g_inv[w][b][c8];
    float sc = (w == 0) ? 0.125f : 1.0f;

    __align__(16) __half2 o[4];
#pragma unroll
    for (int j = 0; j < 4; j++) {
        float2 f = __half22float2(hp[j]);
        o[j] = __floats2half2_rn(f.x * ip[2 * j] * sc, f.y * ip[2 * j + 1] * sc);
    }
    *(uint4*)&g_nrm16[w][m][c8] = *(uint4*)o;
}

// ================= flash attention: mma.sync fp16, BQ=BKV=64, 4 warps =================
#define QSTR 72

__global__ __launch_bounds__(128) void flash_kernel()
{
    __shared__ __align__(16) __half Qs[64 * QSTR];
    __shared__ __align__(16) __half Ks[64 * QSTR];
    __shared__ __align__(16) __half Vs[64 * QSTR];

    int bh = blockIdx.y;
    int b = bh >> 3, h = bh & 7;
    int q0 = blockIdx.x * 64;
    int tid = threadIdx.x;
    int lane = tid & 31, wrp = tid >> 5;
    int grp = lane >> 2, tig = lane & 3;

    u32 qb = (u32)__cvta_generic_to_shared(Qs);
    u32 kb = (u32)__cvta_generic_to_shared(Ks);
    u32 vb = (u32)__cvta_generic_to_shared(Vs);

    // stage Q tile ([b,t,C] layout, head slice)
    {
        const __half* qg = &g_nrm16[0][b * TT + q0][h * DD];
        for (int i = tid; i < 64 * 8; i += 128) {
            int r = i >> 3, c8 = (i & 7) * 8;
            *(uint4*)&Qs[r * QSTR + c8] = *(const uint4*)&qg[r * CC + c8];
        }
    }
    __syncthreads();

    u32 Aq[4][4];
#pragma unroll
    for (int kk = 0; kk < 4; kk++) {
        int row = wrp * 16 + (lane & 15);
        int col = kk * 16 + (lane >> 4) * 8;
        ldsm4(Aq[kk], qb + (u32)(row * QSTR + col) * 2u);
    }

    float m_lo = -1e30f, m_hi = -1e30f, l_lo = 0.f, l_hi = 0.f;
    float O[8][4];
#pragma unroll
    for (int dt = 0; dt < 8; dt++) {
        O[dt][0] = 0.f; O[dt][1] = 0.f; O[dt][2] = 0.f; O[dt][3] = 0.f;
    }

    for (int kv0 = 0; kv0 < TT; kv0 += 64) {
        __syncthreads();
        {
            const __half* kg = &g_nrm16[1][b * TT + kv0][h * DD];
            const __half* vg = &g_nrm16[2][b * TT + kv0][h * DD];
            for (int i = tid; i < 64 * 8; i += 128) {
                int r = i >> 3, c8 = (i & 7) * 8;
                *(uint4*)&Ks[r * QSTR + c8] = *(const uint4*)&kg[r * CC + c8];
                *(uint4*)&Vs[r * QSTR + c8] = *(const uint4*)&vg[r * CC + c8];
            }
        }
        __syncthreads();

        // S = Q @ K^T
        float S[8][4];
#pragma unroll
        for (int jt = 0; jt < 8; jt++) {
            S[jt][0] = 0.f; S[jt][1] = 0.f; S[jt][2] = 0.f; S[jt][3] = 0.f;
        }
#pragma unroll
        for (int kk = 0; kk < 4; kk++) {
            u32 Bk[8][2];
#pragma unroll
            for (int p = 0; p < 4; p++) {
                int row = p * 16 + (lane & 7) + ((lane & 16) ? 8 : 0);
                int col = kk * 16 + ((lane & 8) ? 8 : 0);
                u32 r4[4];
                ldsm4(r4, kb + (u32)(row * QSTR + col) * 2u);
                Bk[2 * p][0] = r4[0]; Bk[2 * p][1] = r4[1];
                Bk[2 * p + 1][0] = r4[2]; Bk[2 * p + 1][1] = r4[3];
            }
#pragma unroll
            for (int jt = 0; jt < 8; jt++) mma16816(S[jt], Aq[kk], Bk[jt]);
        }

        // online softmax
        float mx_lo = -1e30f, mx_hi = -1e30f;
#pragma unroll
        for (int jt = 0; jt < 8; jt++) {
            mx_lo = fmaxf(mx_lo, fmaxf(S[jt][0], S[jt][1]));
            mx_hi = fmaxf(mx_hi, fmaxf(S[jt][2], S[jt][3]));
        }
        mx_lo = qmax(mx_lo);
        mx_hi = qmax(mx_hi);

        float mn_lo = fmaxf(m_lo, mx_lo);
        float mn_hi = fmaxf(m_hi, mx_hi);
        float corr_lo = __expf(m_lo - mn_lo);
        float corr_hi = __expf(m_hi - mn_hi);
        m_lo = mn_lo;
        m_hi = mn_hi;

        float rs_lo = 0.f, rs_hi = 0.f;
#pragma unroll
        for (int jt = 0; jt < 8; jt++) {
            S[jt][0] = __expf(S[jt][0] - m_lo);
            S[jt][1] = __expf(S[jt][1] - m_lo);
            S[jt][2] = __expf(S[jt][2] - m_hi);
            S[jt][3] = __expf(S[jt][3] - m_hi);
            rs_lo += S[jt][0] + S[jt][1];
            rs_hi += S[jt][2] + S[jt][3];
        }
        rs_lo = qsum(rs_lo);
        rs_hi = qsum(rs_hi);
        l_lo = l_lo * corr_lo + rs_lo;
        l_hi = l_hi * corr_hi + rs_hi;

#pragma unroll
        for (int dt = 0; dt < 8; dt++) {
            O[dt][0] *= corr_lo; O[dt][1] *= corr_lo;
            O[dt][2] *= corr_hi; O[dt][3] *= corr_hi;
        }

        // O += P @ V
#pragma unroll
        for (int kk = 0; kk < 4; kk++) {
            u32 Pa[4];
            Pa[0] = pack_half2(S[2 * kk][0],     S[2 * kk][1]);
            Pa[1] = pack_half2(S[2 * kk][2],     S[2 * kk][3]);
            Pa[2] = pack_half2(S[2 * kk + 1][0], S[2 * kk + 1][1]);
            Pa[3] = pack_half2(S[2 * kk + 1][2], S[2 * kk + 1][3]);
#pragma unroll
            for (int p = 0; p < 4; p++) {
                int row = kk * 16 + (lane & 15);
                int col = p * 16 + (lane >> 4) * 8;
                u32 r4[4];
                ldsm4t(r4, vb + (u32)(row * QSTR + col) * 2u);
                u32 Bv0[2]; Bv0[0] = r4[0]; Bv0[1] = r4[1];
                u32 Bv1[2]; Bv1[0] = r4[2]; Bv1[1] = r4[3];
                mma16816(O[2 * p],     Pa, Bv0);
                mma16816(O[2 * p + 1], Pa, Bv1);
            }
        }
    }

    // epilogue: divide by l, write fp16 [b,t,C]
    float il_lo = 1.0f / l_lo;
    float il_hi = 1.0f / l_hi;
    int r_lo = q0 + wrp * 16 + grp;
    int r_hi = r_lo + 8;
#pragma unroll
    for (int dt = 0; dt < 8; dt++) {
        int col = h * DD + dt * 8 + 2 * tig;
        *(__half2*)&g_attn16[b * TT + r_lo][col] =
            __floats2half2_rn(O[dt][0] * il_lo, O[dt][1] * il_lo);
        *(__half2*)&g_attn16[b * TT + r_hi][col] =
            __floats2half2_rn(O[dt][2] * il_hi, O[dt][3] * il_hi);
    }
}

// ======================================================================
extern "C" void kernel_launch(void* const* d_in, const int* in_sizes, int n_in,
                              void* d_out, int out_size)
{
    const float* hs = (const float*)d_in[0];
    const float* Wq = (const float*)d_in[1];
    const float* Wk = (const float*)d_in[2];
    const float* Wv = (const float*)d_in[3];
    const float* Wo = (const float*)d_in[4];
    const float* bo = (const float*)d_in[5];
    float* out = (float*)d_out;

    __half* hs16; cudaGetSymbolAddress((void**)&hs16, g_hs16);
    __half* w16;  cudaGetSymbolAddress((void**)&w16,  g_w16);

    // 0) fp32 -> fp16 conversions
    f2h_kernel<<<MM * CC / 2048, 256>>>(hs, hs16, MM * CC);
    f2h_kernel<<<CC * CC / 2048, 256>>>(Wq, w16 + 0 * CC * CC, CC * CC);
    f2h_kernel<<<CC * CC / 2048, 256>>>(Wk, w16 + 1 * CC * CC, CC * CC);
    f2h_kernel<<<CC * CC / 2048, 256>>>(Wv, w16 + 2 * CC * CC, CC * CC);
    f2h_kernel<<<CC * CC / 2048, 256>>>(Wo, w16 + 3 * CC * CC, CC * CC);
    // 1) q/k/v projections (fp16 tensor cores)
    gemm16_qkv_kernel<<<dim3(64, 4, 3), 256>>>();
    // 2) pixel-norm stats (over token axis)
    sumsq_kernel<<<dim3(16, 4, 3), 512>>>();
    finalize_inv_kernel<<<12, 512>>>();
    // 3) normalize (fold 1/sqrt(d) into q)
    normalize_kernel<<<6144, 256>>>();
    // 4) flash attention (fp16 tensor cores)
    flash_kernel<<<dim3(32, 32), 128>>>();
    // 5) output projection + bias + residual (fp16 TC, fp32 epilogue)
    gemm16_out_kernel<<<dim3(64, 4), 256>>>(bo, hs, out);
}

// round 7
// speedup vs baseline: 4.9641x; 1.0859x over previous
#include <cuda_runtime.h>
#include <cuda_fp16.h>
#include <stdint.h>
#include <math.h>

#define BB 4
#define TT 2048
#define CC 512
#define HH 8
#define DD 64
#define BH (BB*HH)
#define MM (BB*TT)
#define EPSV 1e-4f

typedef unsigned int u32;

// ---------------- scratch (static device globals; no allocation) ----------------
__device__ __half g_hs16[MM][CC];           // hidden states fp16
__device__ __half g_w16[4][CC][CC];         // Wq,Wk,Wv,Wo fp16
__device__ __half g_raw16[3][MM][CC];       // raw q/k/v projections fp16
__device__ __half g_attn16[MM][CC];         // attention output fp16
__device__ float g_sspart[16][3][BB][CC];   // partial column sum-of-squares
__device__ float g_inv[3][BB][CC];          // 1/sqrt(mean+eps) per (w,b,channel)

// ---------------- mma/ldmatrix primitives ----------------
__device__ __forceinline__ void mma16816(float* c, const u32* a, const u32* b)
{
    asm volatile(
        "mma.sync.aligned.m16n8k16.row.col.f32.f16.f16.f32 "
        "{%0,%1,%2,%3}, {%4,%5,%6,%7}, {%8,%9}, {%0,%1,%2,%3};"
        : "+f"(c[0]), "+f"(c[1]), "+f"(c[2]), "+f"(c[3])
        : "r"(a[0]), "r"(a[1]), "r"(a[2]), "r"(a[3]), "r"(b[0]), "r"(b[1]));
}

__device__ __forceinline__ void ldsm4(u32* r, u32 addr)
{
    asm volatile("ldmatrix.sync.aligned.m8n8.x4.shared.b16 {%0,%1,%2,%3}, [%4];"
                 : "=r"(r[0]), "=r"(r[1]), "=r"(r[2]), "=r"(r[3]) : "r"(addr));
}

__device__ __forceinline__ void ldsm4t(u32* r, u32 addr)
{
    asm volatile("ldmatrix.sync.aligned.m8n8.x4.trans.shared.b16 {%0,%1,%2,%3}, [%4];"
                 : "=r"(r[0]), "=r"(r[1]), "=r"(r[2]), "=r"(r[3]) : "r"(addr));
}

__device__ __forceinline__ u32 pack_half2(float lo, float hi)
{
    u32 d;
    asm("cvt.rn.f16x2.f32 %0, %1, %2;" : "=r"(d) : "f"(hi), "f"(lo));
    return d;
}

__device__ __forceinline__ float qmax(float v)
{
    v = fmaxf(v, __shfl_xor_sync(0xffffffffu, v, 1));
    v = fmaxf(v, __shfl_xor_sync(0xffffffffu, v, 2));
    return v;
}

__device__ __forceinline__ float qsum(float v)
{
    v += __shfl_xor_sync(0xffffffffu, v, 1);
    v += __shfl_xor_sync(0xffffffffu, v, 2);
    return v;
}

__device__ __forceinline__ void cp16(u32 dst, const void* src)
{
    asm volatile("cp.async.cg.shared.global [%0], [%1], 16;" :: "r"(dst), "l"(src));
}

// ---------------- fp32 -> fp16 bulk convert ----------------
__global__ __launch_bounds__(256) void f2h_kernel(const float* __restrict__ src,
                                                  __half* __restrict__ dst, int n)
{
    int i = (blockIdx.x * 256 + threadIdx.x) * 8;
    if (i >= n) return;
    float4 a = *(const float4*)(src + i);
    float4 b = *(const float4*)(src + i + 4);
    __align__(16) __half2 o[4];
    o[0] = __floats2half2_rn(a.x, a.y);
    o[1] = __floats2half2_rn(a.z, a.w);
    o[2] = __floats2half2_rn(b.x, b.y);
    o[3] = __floats2half2_rn(b.z, b.w);
    *(uint4*)(dst + i) = *(uint4*)o;
}

__global__ __launch_bounds__(256) void f2h4_kernel(const float* __restrict__ s0,
                                                   const float* __restrict__ s1,
                                                   const float* __restrict__ s2,
                                                   const float* __restrict__ s3)
{
    const float* src = (blockIdx.y == 0) ? s0 : ((blockIdx.y == 1) ? s1
                     : ((blockIdx.y == 2) ? s2 : s3));
    __half* dst = &g_w16[blockIdx.y][0][0];
    int i = (blockIdx.x * 256 + threadIdx.x) * 8;
    float4 a = *(const float4*)(src + i);
    float4 b = *(const float4*)(src + i + 4);
    __align__(16) __half2 o[4];
    o[0] = __floats2half2_rn(a.x, a.y);
    o[1] = __floats2half2_rn(a.z, a.w);
    o[2] = __floats2half2_rn(b.x, b.y);
    o[3] = __floats2half2_rn(b.z, b.w);
    *(uint4*)(dst + i) = *(uint4*)o;
}

// ================= fp16 tensor-core GEMM: 128x128 tile, K-step 64, 256 thr =================
#define ASTR 72
#define BSTR 136

struct GemmAcc { float a[2][8][4]; };

__device__ __forceinline__ void gemm16_core(const __half* __restrict__ A,
                                            const __half* __restrict__ Bw,
                                            int bm0, int bn0,
                                            __half* As, __half* Bs,
                                            GemmAcc& acc)
{
    int tid = threadIdx.x;
    int lane = tid & 31, wrp = tid >> 5;
    int wm = wrp & 3, wn = wrp >> 2;

    u32 as_b = (u32)__cvta_generic_to_shared(As);
    u32 bs_b = (u32)__cvta_generic_to_shared(Bs);

#pragma unroll
    for (int mt = 0; mt < 2; mt++)
#pragma unroll
        for (int nt = 0; nt < 8; nt++) {
            acc.a[mt][nt][0] = 0.f; acc.a[mt][nt][1] = 0.f;
            acc.a[mt][nt][2] = 0.f; acc.a[mt][nt][3] = 0.f;
        }

    uint4 ra[4], rb[4];
#pragma unroll
    for (int p = 0; p < 4; p++) {
        int idx = p * 256 + tid;
        int r = idx >> 3, c8 = (idx & 7) * 8;
        ra[p] = *(const uint4*)&A[(bm0 + r) * CC + c8];
    }
#pragma unroll
    for (int p = 0; p < 4; p++) {
        int idx = p * 256 + tid;
        int r = idx >> 4, c8 = (idx & 15) * 8;
        rb[p] = *(const uint4*)&Bw[r * CC + bn0 + c8];
    }

    for (int it = 0; it < 8; it++) {
        __syncthreads();
#pragma unroll
        for (int p = 0; p < 4; p++) {
            int idx = p * 256 + tid;
            int r = idx >> 3, c8 = (idx & 7) * 8;
            *(uint4*)&As[r * ASTR + c8] = ra[p];
        }
#pragma unroll
        for (int p = 0; p < 4; p++) {
            int idx = p * 256 + tid;
            int r = idx >> 4, c8 = (idx & 15) * 8;
            *(uint4*)&Bs[r * BSTR + c8] = rb[p];
        }
        __syncthreads();

        if (it < 7) {
            int k0 = (it + 1) * 64;
#pragma unroll
            for (int p = 0; p < 4; p++) {
                int idx = p * 256 + tid;
                int r = idx >> 3, c8 = (idx & 7) * 8;
                ra[p] = *(const uint4*)&A[(bm0 + r) * CC + k0 + c8];
            }
#pragma unroll
            for (int p = 0; p < 4; p++) {
                int idx = p * 256 + tid;
                int r = idx >> 4, c8 = (idx & 15) * 8;
                rb[p] = *(const uint4*)&Bw[(k0 + r) * CC + bn0 + c8];
            }
        }

#pragma unroll
        for (int kk = 0; kk < 4; kk++) {
            u32 Af[2][4];
#pragma unroll
            for (int mt = 0; mt < 2; mt++) {
                int row = wm * 32 + mt * 16 + (lane & 15);
                int col = kk * 16 + (lane >> 4) * 8;
                ldsm4(Af[mt], as_b + (u32)(row * ASTR + col) * 2u);
            }
            u32 Bf[8][2];
#pragma unroll
            for (int p = 0; p < 4; p++) {
                int row = kk * 16 + (lane & 15);
                int col = wn * 64 + p * 16 + (lane >> 4) * 8;
                u32 r4[4];
                ldsm4t(r4, bs_b + (u32)(row * BSTR + col) * 2u);
                Bf[2 * p][0] = r4[0]; Bf[2 * p][1] = r4[1];
                Bf[2 * p + 1][0] = r4[2]; Bf[2 * p + 1][1] = r4[3];
            }
#pragma unroll
            for (int mt = 0; mt < 2; mt++)
#pragma unroll
                for (int nt = 0; nt < 8; nt++)
                    mma16816(acc.a[mt][nt], Af[mt], Bf[nt]);
        }
    }
}

__global__ __launch_bounds__(256) void gemm16_qkv_kernel()
{
    __shared__ __align__(16) __half As[128 * ASTR];
    __shared__ __align__(16) __half Bs[64 * BSTR];

    int w = blockIdx.z;
    int bm0 = blockIdx.x * 128, bn0 = blockIdx.y * 128;

    GemmAcc acc;
    gemm16_core(&g_hs16[0][0], &g_w16[w][0][0], bm0, bn0, As, Bs, acc);

    __half* Cout = &g_raw16[w][0][0];
    int tid = threadIdx.x;
    int lane = tid & 31, wrp = tid >> 5;
    int wm = wrp & 3, wn = wrp >> 2;
    int grp = lane >> 2, tig = lane & 3;

#pragma unroll
    for (int mt = 0; mt < 2; mt++)
#pragma unroll
        for (int nt = 0; nt < 8; nt++) {
            int m = bm0 + wm * 32 + mt * 16 + grp;
            int n = bn0 + wn * 64 + nt * 8 + 2 * tig;
            *(__half2*)&Cout[m * CC + n] =
                __floats2half2_rn(acc.a[mt][nt][0], acc.a[mt][nt][1]);
            *(__half2*)&Cout[(m + 8) * CC + n] =
                __floats2half2_rn(acc.a[mt][nt][2], acc.a[mt][nt][3]);
        }
}

__global__ __launch_bounds__(256) void gemm16_out_kernel(
    const float* __restrict__ bo,
    const float* __restrict__ hs,
    float* __restrict__ out)
{
    __shared__ __align__(16) __half As[128 * ASTR];
    __shared__ __align__(16) __half Bs[64 * BSTR];

    int bm0 = blockIdx.x * 128, bn0 = blockIdx.y * 128;

    GemmAcc acc;
    gemm16_core(&g_attn16[0][0], &g_w16[3][0][0], bm0, bn0, As, Bs, acc);

    int tid = threadIdx.x;
    int lane = tid & 31, wrp = tid >> 5;
    int wm = wrp & 3, wn = wrp >> 2;
    int grp = lane >> 2, tig = lane & 3;

#pragma unroll
    for (int mt = 0; mt < 2; mt++)
#pragma unroll
        for (int nt = 0; nt < 8; nt++) {
            int m = bm0 + wm * 32 + mt * 16 + grp;
            int n = bn0 + wn * 64 + nt * 8 + 2 * tig;
            float2 bv = *(const float2*)&bo[n];
            float2 r0 = *(const float2*)&hs[m * CC + n];
            float2 r1 = *(const float2*)&hs[(m + 8) * CC + n];
            float2 o0 = make_float2(acc.a[mt][nt][0] + bv.x + r0.x,
                                    acc.a[mt][nt][1] + bv.y + r0.y);
            float2 o1 = make_float2(acc.a[mt][nt][2] + bv.x + r1.x,
                                    acc.a[mt][nt][3] + bv.y + r1.y);
            *(float2*)&out[m * CC + n] = o0;
            *(float2*)&out[(m + 8) * CC + n] = o1;
        }
}

// ================= pixel-norm stats =================
__global__ __launch_bounds__(512) void sumsq_kernel()
{
    int c = threadIdx.x;
    int chunk = blockIdx.x;
    int b = blockIdx.y;
    int w = blockIdx.z;
    const __half* p = &g_raw16[w][b * TT + chunk * (TT / 16)][0];
    float s = 0.f;
#pragma unroll 4
    for (int t = 0; t < TT / 16; t++) {
        float x = __half2float(p[t * CC + c]);
        s += x * x;
    }
    g_sspart[chunk][w][b][c] = s;
}

__global__ __launch_bounds__(512) void finalize_inv_kernel()
{
    int c = threadIdx.x;
    int b = blockIdx.x & 3;
    int w = blockIdx.x >> 2;
    float s = 0.f;
#pragma unroll
    for (int ch = 0; ch < 16; ch++) s += g_sspart[ch][w][b][c];
    g_inv[w][b][c] = rsqrtf(s * (1.0f / TT) + EPSV);
}

// ================= flash attention: BQ=128, KV=64 double-buffered cp.async =================
// Norm scales folded: Q_eff = q_raw*invq*invk*0.125 (contraction channel), K/V raw,
// V's scale applied on the output channel in the epilogue.
#define QSTR 72
#define FL_Q_HALFS   (128 * QSTR)
#define FL_KV_HALFS  (64 * QSTR)
#define FL_SMEM_BYTES ((FL_Q_HALFS + 4 * FL_KV_HALFS) * 2)

__global__ __launch_bounds__(256) void flash_kernel()
{
    extern __shared__ __align__(16) __half sm16[];
    __half* Qs = sm16;
    __half* Ks = sm16 + FL_Q_HALFS;
    __half* Vs = sm16 + FL_Q_HALFS + 2 * FL_KV_HALFS;

    int bh = blockIdx.y;
    int b = bh >> 3, h = bh & 7;
    int q0 = blockIdx.x * 128;
    int tid = threadIdx.x;
    int lane = tid & 31, wrp = tid >> 5;
    int grp = lane >> 2, tig = lane & 3;

    u32 qb = (u32)__cvta_generic_to_shared(Qs);
    u32 kb = (u32)__cvta_generic_to_shared(Ks);
    u32 vb = (u32)__cvta_generic_to_shared(Vs);

    // ---- stage Q with fused (invq*invk*0.125) per-channel scale ----
    {
        const __half* qg = &g_raw16[0][b * TT + q0][h * DD];
        const float* iq = &g_inv[0][b][h * DD];
        const float* ik = &g_inv[1][b][h * DD];
        for (int i = tid; i < 128 * 8; i += 256) {
            int r = i >> 3, c8 = (i & 7) * 8;
            uint4 raw = *(const uint4*)&qg[r * CC + c8];
            __half2* hp = (__half2*)&raw;
            __align__(16) __half2 o[4];
#pragma unroll
            for (int j = 0; j < 4; j++) {
                float2 f = __half22float2(hp[j]);
                float s0 = iq[c8 + 2 * j] * ik[c8 + 2 * j] * 0.125f;
                float s1 = iq[c8 + 2 * j + 1] * ik[c8 + 2 * j + 1] * 0.125f;
                o[j] = __floats2half2_rn(f.x * s0, f.y * s1);
            }
            *(uint4*)&Qs[r * QSTR + c8] = *(uint4*)o;
        }
    }
    __syncthreads();

    u32 Aq[4][4];
#pragma unroll
    for (int kk = 0; kk < 4; kk++) {
        int row = wrp * 16 + (lane & 15);
        int col = kk * 16 + (lane >> 4) * 8;
        ldsm4(Aq[kk], qb + (u32)(row * QSTR + col) * 2u);
    }

    const __half* kgb = &g_raw16[1][b * TT][h * DD];
    const __half* vgb = &g_raw16[2][b * TT][h * DD];

#define STAGE(bufidx, kv0) do {                                              \
        const __half* kg = kgb + (size_t)(kv0) * CC;                         \
        const __half* vg = vgb + (size_t)(kv0) * CC;                         \
        u32 kd = kb + (u32)(bufidx) * FL_KV_HALFS * 2u;                      \
        u32 vd = vb + (u32)(bufidx) * FL_KV_HALFS * 2u;                      \
        for (int i = tid; i < 512; i += 256) {                               \
            int r = i >> 3, c8 = (i & 7) * 8;                                \
            cp16(kd + (u32)(r * QSTR + c8) * 2u, kg + r * CC + c8);          \
            cp16(vd + (u32)(r * QSTR + c8) * 2u, vg + r * CC + c8);          \
        }                                                                    \
        asm volatile("cp.async.commit_group;" ::: "memory");                 \
    } while (0)

    float m_lo = -1e30f, m_hi = -1e30f, l_lo = 0.f, l_hi = 0.f;
    float O[8][4];
#pragma unroll
    for (int dt = 0; dt < 8; dt++) {
        O[dt][0] = 0.f; O[dt][1] = 0.f; O[dt][2] = 0.f; O[dt][3] = 0.f;
    }

    STAGE(0, 0);

    for (int it = 0; it < 32; it++) {
        if (it < 31) {
            STAGE((it + 1) & 1, (it + 1) * 64);
            asm volatile("cp.async.wait_group 1;" ::: "memory");
        } else {
            asm volatile("cp.async.wait_group 0;" ::: "memory");
        }
        __syncthreads();

        u32 kbb = kb + (u32)(it & 1) * FL_KV_HALFS * 2u;
        u32 vbb = vb + (u32)(it & 1) * FL_KV_HALFS * 2u;

        // ---- S = Q_eff @ K_raw^T ----
        float S[8][4];
#pragma unroll
        for (int jt = 0; jt < 8; jt++) {
            S[jt][0] = 0.f; S[jt][1] = 0.f; S[jt][2] = 0.f; S[jt][3] = 0.f;
        }
#pragma unroll
        for (int kk = 0; kk < 4; kk++) {
            u32 Bk[8][2];
#pragma unroll
            for (int p = 0; p < 4; p++) {
                int row = p * 16 + (lane & 7) + ((lane & 16) ? 8 : 0);
                int col = kk * 16 + ((lane & 8) ? 8 : 0);
                u32 r4[4];
                ldsm4(r4, kbb + (u32)(row * QSTR + col) * 2u);
                Bk[2 * p][0] = r4[0]; Bk[2 * p][1] = r4[1];
                Bk[2 * p + 1][0] = r4[2]; Bk[2 * p + 1][1] = r4[3];
            }
#pragma unroll
            for (int jt = 0; jt < 8; jt++) mma16816(S[jt], Aq[kk], Bk[jt]);
        }

        // ---- online softmax ----
        float mx_lo = -1e30f, mx_hi = -1e30f;
#pragma unroll
        for (int jt = 0; jt < 8; jt++) {
            mx_lo = fmaxf(mx_lo, fmaxf(S[jt][0], S[jt][1]));
            mx_hi = fmaxf(mx_hi, fmaxf(S[jt][2], S[jt][3]));
        }
        mx_lo = qmax(mx_lo);
        mx_hi = qmax(mx_hi);

        float mn_lo = fmaxf(m_lo, mx_lo);
        float mn_hi = fmaxf(m_hi, mx_hi);
        float corr_lo = __expf(m_lo - mn_lo);
        float corr_hi = __expf(m_hi - mn_hi);
        m_lo = mn_lo;
        m_hi = mn_hi;

        float rs_lo = 0.f, rs_hi = 0.f;
#pragma unroll
        for (int jt = 0; jt < 8; jt++) {
            S[jt][0] = __expf(S[jt][0] - m_lo);
            S[jt][1] = __expf(S[jt][1] - m_lo);
            S[jt][2] = __expf(S[jt][2] - m_hi);
            S[jt][3] = __expf(S[jt][3] - m_hi);
            rs_lo += S[jt][0] + S[jt][1];
            rs_hi += S[jt][2] + S[jt][3];
        }
        rs_lo = qsum(rs_lo);
        rs_hi = qsum(rs_hi);
        l_lo = l_lo * corr_lo + rs_lo;
        l_hi = l_hi * corr_hi + rs_hi;

#pragma unroll
        for (int dt = 0; dt < 8; dt++) {
            O[dt][0] *= corr_lo; O[dt][1] *= corr_lo;
            O[dt][2] *= corr_hi; O[dt][3] *= corr_hi;
        }

        // ---- O += P @ V_raw ----
#pragma unroll
        for (int kk = 0; kk < 4; kk++) {
            u32 Pa[4];
            Pa[0] = pack_half2(S[2 * kk][0],     S[2 * kk][1]);
            Pa[1] = pack_half2(S[2 * kk][2],     S[2 * kk][3]);
            Pa[2] = pack_half2(S[2 * kk + 1][0], S[2 * kk + 1][1]);
            Pa[3] = pack_half2(S[2 * kk + 1][2], S[2 * kk + 1][3]);
#pragma unroll
            for (int p = 0; p < 4; p++) {
                int row = kk * 16 + (lane & 15);
                int col = p * 16 + (lane >> 4) * 8;
                u32 r4[4];
                ldsm4t(r4, vbb + (u32)(row * QSTR + col) * 2u);
                u32 Bv0[2]; Bv0[0] = r4[0]; Bv0[1] = r4[1];
                u32 Bv1[2]; Bv1[0] = r4[2]; Bv1[1] = r4[3];
                mma16816(O[2 * p],     Pa, Bv0);
                mma16816(O[2 * p + 1], Pa, Bv1);
            }
        }
        __syncthreads();
    }

    // ---- epilogue: /l, apply V channel scale, write fp16 ----
    float il_lo = 1.0f / l_lo;
    float il_hi = 1.0f / l_hi;
    const float* iv = &g_inv[2][b][h * DD];
    int r_lo = q0 + wrp * 16 + grp;
    int r_hi = r_lo + 8;
#pragma unroll
    for (int dt = 0; dt < 8; dt++) {
        int col = dt * 8 + 2 * tig;
        float s0 = iv[col], s1 = iv[col + 1];
        *(__half2*)&g_attn16[b * TT + r_lo][h * DD + col] =
            __floats2half2_rn(O[dt][0] * il_lo * s0, O[dt][1] * il_lo * s1);
        *(__half2*)&g_attn16[b * TT + r_hi][h * DD + col] =
            __floats2half2_rn(O[dt][2] * il_hi * s0, O[dt][3] * il_hi * s1);
    }
#undef STAGE
}

// ======================================================================
extern "C" void kernel_launch(void* const* d_in, const int* in_sizes, int n_in,
                              void* d_out, int out_size)
{
    const float* hs = (const float*)d_in[0];
    const float* Wq = (const float*)d_in[1];
    const float* Wk = (const float*)d_in[2];
    const float* Wv = (const float*)d_in[3];
    const float* Wo = (const float*)d_in[4];
    const float* bo = (const float*)d_in[5];
    float* out = (float*)d_out;

    __half* hs16; cudaGetSymbolAddress((void**)&hs16, g_hs16);

    cudaFuncSetAttribute(flash_kernel,
                         cudaFuncAttributeMaxDynamicSharedMemorySize, FL_SMEM_BYTES);

    // 0) fp32 -> fp16 conversions (hs + all 4 weights)
    f2h_kernel<<<MM * CC / 2048, 256>>>(hs, hs16, MM * CC);
    f2h4_kernel<<<dim3(CC * CC / 2048, 4), 256>>>(Wq, Wk, Wv, Wo);
    // 1) q/k/v projections (fp16 tensor cores)
    gemm16_qkv_kernel<<<dim3(64, 4, 3), 256>>>();
    // 2) pixel-norm stats (over token axis)
    sumsq_kernel<<<dim3(16, 4, 3), 512>>>();
    finalize_inv_kernel<<<12, 512>>>();
    // 3) flash attention (norm scales fused; cp.async double-buffered)
    flash_kernel<<<dim3(16, 32), 256, FL_SMEM_BYTES>>>();
    // 4) output projection + bias + residual
    gemm16_out_kernel<<<dim3(64, 4), 256>>>(bo, hs, out);
}